// round 2
// baseline (speedup 1.0000x reference)
#include <cuda_runtime.h>
#include <cstdint>

// FwFM second-order: out[i] = sum_{k<l} S[k,l] * x[k,i] * x[l,i],
// S = 0.5*(W + W^T), i over B*D = 524288 elements.
// Packed-f32x2 version: each thread owns 2 elements held in 64-bit f32x2 regs;
// inner op is one FFMA2 (fma.rn.f32x2) + one broadcast LDS.64 of pre-duplicated S.

#define KF 39
#define NELEM (8192 * 64)        // B*D
#define NPAIR (NELEM / 2)        // 262144 f32x2 elements
#define THREADS 256

__device__ __forceinline__ unsigned long long fma_f32x2(
    unsigned long long a, unsigned long long b, unsigned long long c) {
    unsigned long long d;
    asm("fma.rn.f32x2 %0, %1, %2, %3;" : "=l"(d) : "l"(a), "l"(b), "l"(c));
    return d;
}

__global__ __launch_bounds__(THREADS)
void fwfm_kernel(const float* __restrict__ x,
                 const float* __restrict__ W,
                 float* __restrict__ out) {
    // S duplicated into both lanes: Ssh2[l*KF+k] = {s, s} so one LDS.64 feeds FFMA2.
    __shared__ unsigned long long Ssh2[KF * KF];

    for (int i = threadIdx.x; i < KF * KF; i += THREADS) {
        int r = i / KF;
        int c = i - r * KF;
        float s = 0.5f * (W[r * KF + c] + W[c * KF + r]);
        float2 p = make_float2(s, s);
        Ssh2[i] = *reinterpret_cast<unsigned long long*>(&p);
    }
    __syncthreads();

    int i = blockIdx.x * THREADS + threadIdx.x;   // f32x2 index, exact grid

    const unsigned long long* __restrict__ xp =
        reinterpret_cast<const unsigned long long*>(x);

    // Front-batched coalesced loads: 39 x LDG.64 (high MLP).
    unsigned long long v[KF];
#pragma unroll
    for (int k = 0; k < KF; ++k) {
        v[k] = xp[(size_t)k * NPAIR + i];
    }

    unsigned long long y = 0ull;   // {0.0f, 0.0f}
    // Strict-upper-triangle bilinear form, factored:
    //   y += v_l * (sum_{k<l} S[l,k] * v_k), all ops packed f32x2.
#pragma unroll
    for (int l = 1; l < KF; ++l) {
        unsigned long long t = 0ull;
#pragma unroll
        for (int k = 0; k < l; ++k) {
            t = fma_f32x2(Ssh2[l * KF + k], v[k], t);
        }
        y = fma_f32x2(v[l], t, y);
    }

    reinterpret_cast<unsigned long long*>(out)[i] = y;
}

extern "C" void kernel_launch(void* const* d_in, const int* in_sizes, int n_in,
                              void* d_out, int out_size) {
    const float* x = (const float*)d_in[0];   // [39, 8192, 64] fp32
    const float* W = (const float*)d_in[1];   // [39, 39] fp32
    float* out = (float*)d_out;               // [8192, 64] fp32

    fwfm_kernel<<<NPAIR / THREADS, THREADS>>>(x, W, out);
}

// round 3
// speedup vs baseline: 1.2470x; 1.2470x over previous
#include <cuda_runtime.h>

// FwFM second-order: out[i] = sum_{k<l} S[k,l] * x[k,i] * x[l,i],  S = (W+W^T)/2.
// E=4 elements/thread as two packed f32x2 lanes; inner op = 1 broadcast LDS.32
// (1 crossbar phase) + 1 reg-dup (alu pipe) + 2 FFMA2 (packed fp32).

#define KF 39
#define NELEM (8192 * 64)          // B*D floats per field
#define NQUAD (NELEM / 4)          // 131072 quads (16B) per field
#define THREADS 128

typedef unsigned long long ull;

__device__ __forceinline__ ull fma2(ull a, ull b, ull c) {
    ull d;
    asm("fma.rn.f32x2 %0, %1, %2, %3;" : "=l"(d) : "l"(a), "l"(b), "l"(c));
    return d;
}

__device__ __forceinline__ ull dup2(float s) {
    ull d;
    asm("mov.b64 %0, {%1, %1};" : "=l"(d) : "f"(s));
    return d;
}

__global__ __launch_bounds__(THREADS, 2)
void fwfm_kernel(const float* __restrict__ x,
                 const float* __restrict__ W,
                 float* __restrict__ out) {
    __shared__ float Ssh[KF * KF];

    for (int i = threadIdx.x; i < KF * KF; i += THREADS) {
        int r = i / KF;
        int c = i - r * KF;
        Ssh[i] = 0.5f * (W[r * KF + c] + W[c * KF + r]);
    }
    __syncthreads();

    int i = blockIdx.x * THREADS + threadIdx.x;   // quad index, exact grid

    // 39 x LDG.128, fully coalesced (consecutive 16B per thread).
    const ulonglong2* __restrict__ xp = reinterpret_cast<const ulonglong2*>(x);
    ull v0[KF], v1[KF];
#pragma unroll
    for (int k = 0; k < KF; ++k) {
        ulonglong2 q = xp[(size_t)k * NQUAD + i];
        v0[k] = q.x;
        v1[k] = q.y;
    }

    ull y0 = 0ull, y1 = 0ull;
    // y += v_l * (sum_{k<l} S[l,k] * v_k), two independent packed chains.
#pragma unroll
    for (int l = 1; l < KF; ++l) {
        ull t0 = 0ull, t1 = 0ull;
#pragma unroll
        for (int k = 0; k < l; ++k) {
            ull sd = dup2(Ssh[l * KF + k]);   // LDS.32 broadcast + alu dup
            t0 = fma2(sd, v0[k], t0);
            t1 = fma2(sd, v1[k], t1);
        }
        y0 = fma2(v0[l], t0, y0);
        y1 = fma2(v1[l], t1, y1);
    }

    ulonglong2 r;
    r.x = y0;
    r.y = y1;
    reinterpret_cast<ulonglong2*>(out)[i] = r;   // STG.128
}

extern "C" void kernel_launch(void* const* d_in, const int* in_sizes, int n_in,
                              void* d_out, int out_size) {
    const float* x = (const float*)d_in[0];   // [39, 8192, 64] fp32
    const float* W = (const float*)d_in[1];   // [39, 39] fp32
    float* out = (float*)d_out;               // [8192, 64] fp32

    fwfm_kernel<<<NQUAD / THREADS, THREADS>>>(x, W, out);
}